// round 1
// baseline (speedup 1.0000x reference)
#include <cuda_runtime.h>
#include <math.h>

#define B_TOT 16384
#define S_DIM 300
#define A_DIM 30
#define EMB 256
#define M_TOK 8
#define M_PROTO 16
#define H_ENC 256
#define H_DEC 128
#define NT 256
#define ROWS 16
#define NBLK (B_TOT / ROWS)

// Precomputed batch-independent tables
__device__ float G_g[256 * 128];    // G[k][m*16+n], scale folded in
__device__ float c_g[128];          // c[m*16+n]
__device__ float conc_g[M_PROTO * A_DIM];

// ---------------------------------------------------------------------------
// Precompute kernel: G (blocks 0..255), c + conc (block 256)
// ---------------------------------------------------------------------------
__global__ void precompute_kernel(const float* __restrict__ pk,
                                  const float* __restrict__ enc_W2,
                                  const float* __restrict__ enc_b2,
                                  const float* __restrict__ dW1,
                                  const float* __restrict__ db1,
                                  const float* __restrict__ dW2,
                                  const float* __restrict__ db2) {
    const int bk = blockIdx.x;
    const int t = threadIdx.x;  // 128 threads
    if (bk < 256) {
        __shared__ float w2row[2048];
        __shared__ float pks[16 * 256];
        for (int i = t; i < 2048; i += 128) w2row[i] = enc_W2[bk * 2048 + i];
        for (int i = t; i < 4096; i += 128) pks[i] = pk[i];
        __syncthreads();
        const int m = t >> 4, n = t & 15;
        float s = 0.f;
        #pragma unroll 8
        for (int e = 0; e < 256; e++) s += w2row[m * 256 + e] * pks[n * 256 + e];
        G_g[bk * 128 + t] = s * 0.0625f;
    } else {
        // c[m][n]
        if (t < 128) {
            const int m = t >> 4, n = t & 15;
            float s = 0.f;
            for (int e = 0; e < 256; e++) s += enc_b2[m * 256 + e] * pk[n * 256 + e];
            c_g[t] = s * 0.0625f;
        }
        // hd[m][h] then conc[m][a]
        __shared__ float hd[M_PROTO * H_DEC];
        if (t < 128) {
            for (int m = 0; m < M_PROTO; m++) {
                float s = db1[m * H_DEC + t];
                for (int e = 0; e < 256; e++)
                    s += pk[m * 256 + e] * dW1[(m * 256 + e) * H_DEC + t];
                hd[m * H_DEC + t] = fmaxf(s, 0.f);
            }
        }
        __syncthreads();
        for (int idx = t; idx < M_PROTO * A_DIM; idx += 128) {
            const int m = idx / A_DIM, a = idx % A_DIM;
            float s = db2[m * A_DIM + a];
            for (int h = 0; h < H_DEC; h++)
                s += hd[m * H_DEC + h] * dW2[(m * H_DEC + h) * A_DIM + a];
            // softplus = max(x,0) + log1p(exp(-|x|))
            conc_g[idx] = fmaxf(s, 0.f) + log1pf(expf(-fabsf(s)));
        }
    }
}

// ---------------------------------------------------------------------------
// Main fused kernel: 1024 blocks x 256 threads, 16 batch rows per block
// ---------------------------------------------------------------------------
__global__ void __launch_bounds__(NT) main_kernel(
    const float* __restrict__ state, const float* __restrict__ fitness,
    const float* __restrict__ pk, const float* __restrict__ W1,
    const float* __restrict__ b1, const float* __restrict__ ln_g,
    const float* __restrict__ ln_b, const float* __restrict__ tc_W,
    const float* __restrict__ tc_b, const float* __restrict__ tc_cW,
    const float* __restrict__ tc_cb, const float* __restrict__ w_prev,
    float* __restrict__ out) {
    extern __shared__ float sm[];
    float* st    = sm;               // ROWS*304
    float* tcW   = st + ROWS * 304;  // 3072
    float* pks   = tcW + 3072;       // 16*257 (padded vs bank conflicts)
    float* hbuf  = pks + 16 * 257;   // ROWS*256
    float* dng   = hbuf + ROWS * 256; // ROWS*257 (padded)
    float* lgt   = dng + ROWS * 257; // ROWS*128
    float* dds   = lgt + ROWS * 128; // ROWS*16 (dd, later reused as w)
    float* concs = dds + ROWS * 16;  // 480
    float* stats = concs + 480;      // mu[16], rstd[16], crisis[16]

    const int tid = threadIdx.x;
    const int lane = tid & 31;
    const int wid = tid >> 5;
    const int b0 = blockIdx.x * ROWS;
    const unsigned FULL = 0xffffffffu;

    // cooperative loads
    for (int i = tid; i < ROWS * S_DIM; i += NT) {
        int r = i / S_DIM, s = i - r * S_DIM;
        st[r * 304 + s] = state[(b0 + r) * S_DIM + s];
    }
    for (int i = tid; i < 12 * 256; i += NT) tcW[i] = tc_W[i];
    for (int i = tid; i < 16 * 256; i += NT) {
        int n = i >> 8, e = i & 255;
        pks[n * 257 + e] = pk[i];
    }
    for (int i = tid; i < M_PROTO * A_DIM; i += NT) concs[i] = conc_g[i];
    __syncthreads();

    // ---- stage 1: market features + danger + crisis (warp per row pair) ----
    for (int rr = 0; rr < 2; rr++) {
        const int r = wid + rr * 8;
        const float* srow = st + r * 304;
        float p = 0.f, sh = 0.f;
        if (lane < 30) { p = srow[1 + lane]; sh = srow[31 + lane]; }
        float sp = p, spp = p * p, sps = p * sh;
        #pragma unroll
        for (int m2 = 16; m2 >= 1; m2 >>= 1) {
            sp  += __shfl_xor_sync(FULL, sp, m2);
            spp += __shfl_xor_sync(FULL, spp, m2);
            sps += __shfl_xor_sync(FULL, sps, m2);
        }
        const float bal = srow[0];
        const float mean = sp * (1.f / 30.f);
        const float var = fmaxf((spp - 30.f * mean * mean) * (1.f / 29.f), 0.f);
        const float stdv = sqrtf(var) + 1e-8f;
        const float tv = bal + sps;
        const float cash = bal / (tv + 1e-8f);
        float mf[12];
        mf[0] = bal; mf[1] = mean; mf[2] = stdv; mf[3] = cash;
        #pragma unroll
        for (int i = 0; i < 8; i++) mf[4 + i] = srow[61 + 30 * i];
        float cpart = 0.f;
        #pragma unroll
        for (int i = 0; i < 8; i++) {
            const int j = lane + 32 * i;
            float a = tc_b[j];
            #pragma unroll
            for (int f = 0; f < 12; f++) a += mf[f] * tcW[f * 256 + j];
            const float d = tanhf(a);
            dng[r * 257 + j] = d;
            cpart += d * tc_cW[j];
        }
        #pragma unroll
        for (int m2 = 16; m2 >= 1; m2 >>= 1) cpart += __shfl_xor_sync(FULL, cpart, m2);
        if (lane == 0)
            stats[32 + r] = 1.f / (1.f + expf(-(cpart + tc_cb[0])));
    }

    // ---- stage 2: enc_W1 GEMM (thread = output column, 16 rows in regs) ----
    {
        float acc[ROWS];
        #pragma unroll
        for (int r = 0; r < ROWS; r++) acc[r] = 0.f;
        #pragma unroll 4
        for (int s = 0; s < S_DIM; s++) {
            const float w = W1[s * 256 + tid];
            #pragma unroll
            for (int r = 0; r < ROWS; r++) acc[r] += st[r * 304 + s] * w;
        }
        const float bb = b1[tid];
        #pragma unroll
        for (int r = 0; r < ROWS; r++) hbuf[r * 256 + tid] = acc[r] + bb;
    }
    __syncthreads();

    // ---- layernorm stats (warp per row pair) ----
    for (int rr = 0; rr < 2; rr++) {
        const int r = wid + rr * 8;
        float s1 = 0.f, s2 = 0.f;
        #pragma unroll
        for (int i = 0; i < 8; i++) {
            const float v = hbuf[r * 256 + lane + 32 * i];
            s1 += v; s2 += v * v;
        }
        #pragma unroll
        for (int m2 = 16; m2 >= 1; m2 >>= 1) {
            s1 += __shfl_xor_sync(FULL, s1, m2);
            s2 += __shfl_xor_sync(FULL, s2, m2);
        }
        if (lane == 0) {
            const float mu = s1 * (1.f / 256.f);
            const float var = s2 * (1.f / 256.f) - mu * mu;
            stats[r] = mu;
            stats[16 + r] = rsqrtf(fmaxf(var, 0.f) + 1e-5f);
        }
    }
    __syncthreads();
    {
        const float g = ln_g[tid], bb = ln_b[tid];
        #pragma unroll
        for (int r = 0; r < ROWS; r++) {
            const float v = (hbuf[r * 256 + tid] - stats[r]) * stats[16 + r] * g + bb;
            hbuf[r * 256 + tid] = fmaxf(v, 0.f);
        }
    }
    __syncthreads();

    // ---- dd[r][n] = scale * danger[r] . pk[n] ----
    {
        const int r = tid >> 4, n = tid & 15;
        float s = 0.f;
        #pragma unroll 8
        for (int k = 0; k < 256; k++) s += dng[r * 257 + k] * pks[n * 257 + k];
        dds[r * 16 + n] = s * 0.0625f;
    }
    __syncthreads();

    // ---- folded logits GEMM: logits[r][mn] = h[r] . G[:,mn] + c + dd ----
    {
        const int mn = tid & 127, rg = tid >> 7;
        float acc[8];
        #pragma unroll
        for (int q = 0; q < 8; q++) acc[q] = 0.f;
        #pragma unroll 2
        for (int k = 0; k < 256; k++) {
            const float g = G_g[k * 128 + mn];
            #pragma unroll
            for (int q = 0; q < 8; q++) acc[q] += hbuf[(rg + 2 * q) * 256 + k] * g;
        }
        const float cc = c_g[mn];
        const int n = mn & 15;
        #pragma unroll
        for (int q = 0; q < 8; q++) {
            const int r = rg + 2 * q;
            lgt[r * 128 + mn] = acc[q] + cc + dds[r * 16 + n];
        }
    }
    __syncthreads();

    // ---- softmax over protos, weight mixing, action softmax (warp/row) ----
    for (int rr = 0; rr < 2; rr++) {
        const int r = wid + rr * 8;
        const int n = lane & 15;
        const int mh = lane >> 4;
        float wot = 0.f;
        #pragma unroll
        for (int mm = 0; mm < 4; mm++) {
            const int m = mm * 2 + mh;
            const float v = lgt[r * 128 + m * 16 + n];
            float mx = v;
            #pragma unroll
            for (int m2 = 8; m2 >= 1; m2 >>= 1) mx = fmaxf(mx, __shfl_xor_sync(FULL, mx, m2));
            const float e = expf(v - mx);
            float s = e;
            #pragma unroll
            for (int m2 = 8; m2 >= 1; m2 >>= 1) s += __shfl_xor_sync(FULL, s, m2);
            wot += e / s;
        }
        wot += __shfl_xor_sync(FULL, wot, 16);
        wot *= 0.125f;

        // replicator weights
        const float f = fitness[(b0 + r) * 16 + n];
        float wr = w_prev[n] * expf(0.1f * f);
        float swr = wr;
        #pragma unroll
        for (int m2 = 8; m2 >= 1; m2 >>= 1) swr += __shfl_xor_sync(FULL, swr, m2);
        wr /= (swr + 1e-8f);

        const float crisis = stats[32 + r];
        const float alpha = 0.06f + 0.24f * (1.f - crisis);
        float w = alpha * wot + (1.f - alpha) * wr;
        float sw = w;
        #pragma unroll
        for (int m2 = 8; m2 >= 1; m2 >>= 1) sw += __shfl_xor_sync(FULL, sw, m2);
        w /= (sw + 1e-8f);
        if (lane < 16) dds[r * 16 + n] = w;  // reuse dds as w row (own rows only)
        __syncwarp();

        // mixed = w @ conc + 1 ; softmax over 30 actions; renormalize
        float mix = __int_as_float(0xff800000);  // -inf
        if (lane < 30) {
            mix = 1.f;
            #pragma unroll
            for (int m = 0; m < 16; m++) mix += dds[r * 16 + m] * concs[m * 30 + lane];
        }
        float mx = mix;
        #pragma unroll
        for (int m2 = 16; m2 >= 1; m2 >>= 1) mx = fmaxf(mx, __shfl_xor_sync(FULL, mx, m2));
        float e = (lane < 30) ? expf(mix - mx) : 0.f;
        float s = e;
        #pragma unroll
        for (int m2 = 16; m2 >= 1; m2 >>= 1) s += __shfl_xor_sync(FULL, s, m2);
        float p = e / s;
        float sp = p;
        #pragma unroll
        for (int m2 = 16; m2 >= 1; m2 >>= 1) sp += __shfl_xor_sync(FULL, sp, m2);
        p = p / (sp + 1e-8f);
        if (lane < 30) out[(b0 + r) * 30 + lane] = p;
    }
}

// ---------------------------------------------------------------------------
extern "C" void kernel_launch(void* const* d_in, const int* in_sizes, int n_in,
                              void* d_out, int out_size) {
    const float* state   = (const float*)d_in[0];
    const float* fitness = (const float*)d_in[1];
    const float* pk      = (const float*)d_in[2];
    const float* W1      = (const float*)d_in[3];
    const float* b1      = (const float*)d_in[4];
    const float* ln_g    = (const float*)d_in[5];
    const float* ln_b    = (const float*)d_in[6];
    const float* W2      = (const float*)d_in[7];
    const float* b2      = (const float*)d_in[8];
    const float* dW1     = (const float*)d_in[9];
    const float* db1     = (const float*)d_in[10];
    const float* dW2     = (const float*)d_in[11];
    const float* db2     = (const float*)d_in[12];
    const float* tcW     = (const float*)d_in[13];
    const float* tcb     = (const float*)d_in[14];
    const float* tccW    = (const float*)d_in[15];
    const float* tccb    = (const float*)d_in[16];
    // d_in[17] tc_zW, d_in[18] tc_zb: dead code in reference (z unused)
    const float* w_prev  = (const float*)d_in[19];
    float* out = (float*)d_out;

    precompute_kernel<<<257, 128>>>(pk, W2, b2, dW1, db1, dW2, db2);

    const int smem_bytes = (ROWS * 304 + 3072 + 16 * 257 + ROWS * 256 +
                            ROWS * 257 + ROWS * 128 + ROWS * 16 + 480 + 48) *
                           (int)sizeof(float);
    cudaFuncSetAttribute(main_kernel, cudaFuncAttributeMaxDynamicSharedMemorySize,
                         smem_bytes);
    main_kernel<<<NBLK, NT, smem_bytes>>>(state, fitness, pk, W1, b1, ln_g, ln_b,
                                          tcW, tcb, tccW, tccb, w_prev, out);
}

// round 2
// speedup vs baseline: 1.2254x; 1.2254x over previous
#include <cuda_runtime.h>
#include <math.h>

#define B_TOT 16384
#define S_DIM 300
#define A_DIM 30
#define EMB 256
#define M_PROTO 16
#define NT 256
#define ROWS 16
#define NBLK (B_TOT / ROWS)

// Precomputed batch-independent tables
__device__ float G_g[256 * 128];    // G[k][m*16+n], scale folded in
__device__ float c_g[128];          // c[m*16+n]
__device__ float conc_g[M_PROTO * A_DIM];

// ---------------------------------------------------------------------------
// Precompute: blocks 0..255 -> G row k (256 thr, split-e + padded smem),
//             block 256     -> c_g + conc_g
// ---------------------------------------------------------------------------
__global__ void __launch_bounds__(256) precompute_kernel(
    const float* __restrict__ pk, const float* __restrict__ enc_W2,
    const float* __restrict__ enc_b2, const float* __restrict__ dW1,
    const float* __restrict__ db1, const float* __restrict__ dW2,
    const float* __restrict__ db2) {
    const int bk = blockIdx.x;
    const int t = threadIdx.x;  // 256 threads
    if (bk < 256) {
        __shared__ float w2row[2048];
        __shared__ float pks[16 * 257];   // padded: conflict-free across n
        __shared__ float part[256];
        for (int i = t; i < 2048; i += 256) w2row[i] = enc_W2[bk * 2048 + i];
        for (int i = t; i < 4096; i += 256)
            pks[(i >> 8) * 257 + (i & 255)] = pk[i];
        __syncthreads();
        const int mn = t & 127, half = t >> 7;
        const int m = mn >> 4, n = mn & 15;
        const float* wr = w2row + m * 256 + half * 128;
        const float* pr = pks + n * 257 + half * 128;
        float s = 0.f;
        #pragma unroll 8
        for (int e = 0; e < 128; e++) s += wr[e] * pr[e];
        part[t] = s;
        __syncthreads();
        if (t < 128) G_g[bk * 128 + t] = (part[t] + part[t + 128]) * 0.0625f;
    } else {
        if (t < 128) {
            const int m = t >> 4, n = t & 15;
            float s = 0.f;
            for (int e = 0; e < 256; e++)
                s += enc_b2[m * 256 + e] * pk[n * 256 + e];
            c_g[t] = s * 0.0625f;
        }
        __shared__ float hd[M_PROTO * 128];
        if (t < 128) {
            for (int m = 0; m < M_PROTO; m++) {
                float s = db1[m * 128 + t];
                for (int e = 0; e < 256; e++)
                    s += pk[m * 256 + e] * dW1[(m * 256 + e) * 128 + t];
                hd[m * 128 + t] = fmaxf(s, 0.f);
            }
        }
        __syncthreads();
        for (int idx = t; idx < M_PROTO * A_DIM; idx += 256) {
            const int m = idx / A_DIM, a = idx % A_DIM;
            float s = db2[m * A_DIM + a];
            for (int h = 0; h < 128; h++)
                s += hd[m * 128 + h] * dW2[(m * 128 + h) * A_DIM + a];
            conc_g[idx] = fmaxf(s, 0.f) + log1pf(expf(-fabsf(s)));
        }
    }
}

// ---------------------------------------------------------------------------
// Main fused kernel: 1024 blocks x 256 threads, 16 batch rows per block
// smem ~55.6KB -> 2 blocks/SM (launch_bounds caps regs at 128)
// ---------------------------------------------------------------------------
__global__ void __launch_bounds__(NT, 2) main_kernel(
    const float* __restrict__ state, const float* __restrict__ fitness,
    const float* __restrict__ pk, const float* __restrict__ W1,
    const float* __restrict__ b1, const float* __restrict__ ln_g,
    const float* __restrict__ ln_b, const float* __restrict__ tc_W,
    const float* __restrict__ tc_b, const float* __restrict__ tc_cW,
    const float* __restrict__ tc_cb, const float* __restrict__ w_prev,
    float* __restrict__ out) {
    extern __shared__ float sm[];
    float* st    = sm;                 // ROWS*304 = 4864  (later aliased by lgt)
    float* hbuf  = st + ROWS * 304;    // ROWS*256 = 4096
    float* dng   = hbuf + ROWS * 256;  // ROWS*260 = 4160 (padded, 16B-aligned rows)
    float* dds   = dng + ROWS * 260;   // 256
    float* concs = dds + 256;          // 480
    float* stats = concs + 480;        // 48: rstd-free: mu[16], rstd[16], crisis[16]
    float* lgt   = st;                 // alias: ROWS*128 = 2048 (st dead by then)

    const int tid = threadIdx.x;
    const int lane = tid & 31;
    const int wid = tid >> 5;
    const int b0 = blockIdx.x * ROWS;
    const unsigned FULL = 0xffffffffu;

    // cooperative loads
    for (int i = tid; i < ROWS * S_DIM; i += NT) {
        int r = i / S_DIM, s = i - r * S_DIM;
        st[r * 304 + s] = state[(b0 + r) * S_DIM + s];
    }
    for (int i = tid; i < M_PROTO * A_DIM; i += NT) concs[i] = conc_g[i];
    __syncthreads();

    // ---- stage 1: market features + danger + crisis (warp per row pair) ----
    for (int rr = 0; rr < 2; rr++) {
        const int r = wid + rr * 8;
        const float* srow = st + r * 304;
        float p = 0.f, sh = 0.f;
        if (lane < 30) { p = srow[1 + lane]; sh = srow[31 + lane]; }
        float sp = p, spp = p * p, sps = p * sh;
        #pragma unroll
        for (int m2 = 16; m2 >= 1; m2 >>= 1) {
            sp  += __shfl_xor_sync(FULL, sp, m2);
            spp += __shfl_xor_sync(FULL, spp, m2);
            sps += __shfl_xor_sync(FULL, sps, m2);
        }
        const float bal = srow[0];
        const float mean = sp * (1.f / 30.f);
        const float var = fmaxf((spp - 30.f * mean * mean) * (1.f / 29.f), 0.f);
        const float stdv = sqrtf(var) + 1e-8f;
        const float tv = bal + sps;
        const float cash = bal / (tv + 1e-8f);
        float mf[12];
        mf[0] = bal; mf[1] = mean; mf[2] = stdv; mf[3] = cash;
        #pragma unroll
        for (int i = 0; i < 8; i++) mf[4 + i] = srow[61 + 30 * i];
        float cpart = 0.f;
        #pragma unroll
        for (int i = 0; i < 8; i++) {
            const int j = lane + 32 * i;
            float a = tc_b[j];
            #pragma unroll
            for (int f = 0; f < 12; f++) a += mf[f] * tc_W[f * 256 + j];
            const float d = tanhf(a);
            dng[r * 260 + j] = d;
            cpart += d * tc_cW[j];
        }
        #pragma unroll
        for (int m2 = 16; m2 >= 1; m2 >>= 1) cpart += __shfl_xor_sync(FULL, cpart, m2);
        if (lane == 0)
            stats[32 + r] = 1.f / (1.f + expf(-(cpart + tc_cb[0])));
    }
    __syncthreads();

    // ---- dd[r][n] = scale * danger[r] . pk[n]  (float4, pk via L2) ----
    {
        const int r = tid >> 4, n = tid & 15;
        const float* dr = dng + r * 260;
        const float4* pr = (const float4*)(pk + n * 256);
        float s = 0.f;
        #pragma unroll 4
        for (int k4 = 0; k4 < 64; k4++) {
            const float4 d4 = *(const float4*)&dr[k4 * 4];
            const float4 p4 = __ldg(&pr[k4]);
            s += d4.x * p4.x + d4.y * p4.y + d4.z * p4.z + d4.w * p4.w;
        }
        dds[r * 16 + n] = s * 0.0625f;
    }

    // ---- stage 2: enc_W1 GEMM (thread = column, 16 rows in regs, s by 4) ----
    {
        float acc[ROWS];
        #pragma unroll
        for (int r = 0; r < ROWS; r++) acc[r] = 0.f;
        #pragma unroll 2
        for (int s4 = 0; s4 < 75; s4++) {
            const int s = s4 * 4;
            const float w0 = W1[(s + 0) * 256 + tid];
            const float w1 = W1[(s + 1) * 256 + tid];
            const float w2 = W1[(s + 2) * 256 + tid];
            const float w3 = W1[(s + 3) * 256 + tid];
            #pragma unroll
            for (int r = 0; r < ROWS; r++) {
                const float4 sv = *(const float4*)&st[r * 304 + s];
                acc[r] += sv.x * w0 + sv.y * w1 + sv.z * w2 + sv.w * w3;
            }
        }
        const float bb = b1[tid];
        #pragma unroll
        for (int r = 0; r < ROWS; r++) hbuf[r * 256 + tid] = acc[r] + bb;
    }
    __syncthreads();

    // ---- layernorm stats (warp per row pair) ----
    for (int rr = 0; rr < 2; rr++) {
        const int r = wid + rr * 8;
        float s1 = 0.f, s2 = 0.f;
        #pragma unroll
        for (int i = 0; i < 8; i++) {
            const float v = hbuf[r * 256 + lane + 32 * i];
            s1 += v; s2 += v * v;
        }
        #pragma unroll
        for (int m2 = 16; m2 >= 1; m2 >>= 1) {
            s1 += __shfl_xor_sync(FULL, s1, m2);
            s2 += __shfl_xor_sync(FULL, s2, m2);
        }
        if (lane == 0) {
            const float mu = s1 * (1.f / 256.f);
            const float var = s2 * (1.f / 256.f) - mu * mu;
            stats[r] = mu;
            stats[16 + r] = rsqrtf(fmaxf(var, 0.f) + 1e-5f);
        }
    }
    __syncthreads();
    {
        const float g = ln_g[tid], bb = ln_b[tid];
        #pragma unroll
        for (int r = 0; r < ROWS; r++) {
            const float v = (hbuf[r * 256 + tid] - stats[r]) * stats[16 + r] * g + bb;
            hbuf[r * 256 + tid] = fmaxf(v, 0.f);
        }
    }
    __syncthreads();

    // ---- folded logits GEMM: lgt[r][mn] = h[r].G[:,mn] + c + dd (k by 4) ----
    {
        const int mn = tid & 127, rg = tid >> 7;
        float acc[8];
        #pragma unroll
        for (int q = 0; q < 8; q++) acc[q] = 0.f;
        #pragma unroll 2
        for (int k4 = 0; k4 < 64; k4++) {
            const int k = k4 * 4;
            const float g0 = G_g[(k + 0) * 128 + mn];
            const float g1 = G_g[(k + 1) * 128 + mn];
            const float g2 = G_g[(k + 2) * 128 + mn];
            const float g3 = G_g[(k + 3) * 128 + mn];
            #pragma unroll
            for (int q = 0; q < 8; q++) {
                const float4 h4 = *(const float4*)&hbuf[(rg + 2 * q) * 256 + k];
                acc[q] += h4.x * g0 + h4.y * g1 + h4.z * g2 + h4.w * g3;
            }
        }
        const float cc = c_g[mn];
        const int n = mn & 15;
        #pragma unroll
        for (int q = 0; q < 8; q++) {
            const int r = rg + 2 * q;
            lgt[r * 128 + mn] = acc[q] + cc + dds[r * 16 + n];
        }
    }
    __syncthreads();

    // ---- softmax over protos, weight mixing, action softmax (warp/row) ----
    for (int rr = 0; rr < 2; rr++) {
        const int r = wid + rr * 8;
        const int n = lane & 15;
        const int mh = lane >> 4;
        float wot = 0.f;
        #pragma unroll
        for (int mm = 0; mm < 4; mm++) {
            const int m = mm * 2 + mh;
            const float v = lgt[r * 128 + m * 16 + n];
            float mx = v;
            #pragma unroll
            for (int m2 = 8; m2 >= 1; m2 >>= 1) mx = fmaxf(mx, __shfl_xor_sync(FULL, mx, m2));
            const float e = expf(v - mx);
            float s = e;
            #pragma unroll
            for (int m2 = 8; m2 >= 1; m2 >>= 1) s += __shfl_xor_sync(FULL, s, m2);
            wot += e / s;
        }
        wot += __shfl_xor_sync(FULL, wot, 16);
        wot *= 0.125f;

        const float f = fitness[(b0 + r) * 16 + n];
        float wr = w_prev[n] * expf(0.1f * f);
        float swr = wr;
        #pragma unroll
        for (int m2 = 8; m2 >= 1; m2 >>= 1) swr += __shfl_xor_sync(FULL, swr, m2);
        wr /= (swr + 1e-8f);

        const float crisis = stats[32 + r];
        const float alpha = 0.06f + 0.24f * (1.f - crisis);
        float w = alpha * wot + (1.f - alpha) * wr;
        float sw = w;
        #pragma unroll
        for (int m2 = 8; m2 >= 1; m2 >>= 1) sw += __shfl_xor_sync(FULL, sw, m2);
        w /= (sw + 1e-8f);
        if (lane < 16) dds[r * 16 + n] = w;
        __syncwarp();

        float mix = __int_as_float(0xff800000);
        if (lane < 30) {
            mix = 1.f;
            #pragma unroll
            for (int m = 0; m < 16; m++) mix += dds[r * 16 + m] * concs[m * 30 + lane];
        }
        float mx = mix;
        #pragma unroll
        for (int m2 = 16; m2 >= 1; m2 >>= 1) mx = fmaxf(mx, __shfl_xor_sync(FULL, mx, m2));
        float e = (lane < 30) ? expf(mix - mx) : 0.f;
        float s = e;
        #pragma unroll
        for (int m2 = 16; m2 >= 1; m2 >>= 1) s += __shfl_xor_sync(FULL, s, m2);
        float p = e / s;
        float sp = p;
        #pragma unroll
        for (int m2 = 16; m2 >= 1; m2 >>= 1) sp += __shfl_xor_sync(FULL, sp, m2);
        p = p / (sp + 1e-8f);
        if (lane < 30) out[(b0 + r) * 30 + lane] = p;
    }
}

// ---------------------------------------------------------------------------
extern "C" void kernel_launch(void* const* d_in, const int* in_sizes, int n_in,
                              void* d_out, int out_size) {
    const float* state   = (const float*)d_in[0];
    const float* fitness = (const float*)d_in[1];
    const float* pk      = (const float*)d_in[2];
    const float* W1      = (const float*)d_in[3];
    const float* b1      = (const float*)d_in[4];
    const float* ln_g    = (const float*)d_in[5];
    const float* ln_b    = (const float*)d_in[6];
    const float* W2      = (const float*)d_in[7];
    const float* b2      = (const float*)d_in[8];
    const float* dW1     = (const float*)d_in[9];
    const float* db1     = (const float*)d_in[10];
    const float* dW2     = (const float*)d_in[11];
    const float* db2     = (const float*)d_in[12];
    const float* tcW     = (const float*)d_in[13];
    const float* tcb     = (const float*)d_in[14];
    const float* tccW    = (const float*)d_in[15];
    const float* tccb    = (const float*)d_in[16];
    const float* w_prev  = (const float*)d_in[19];
    float* out = (float*)d_out;

    precompute_kernel<<<257, 256>>>(pk, W2, b2, dW1, db1, dW2, db2);

    const int smem_bytes =
        (ROWS * 304 + ROWS * 256 + ROWS * 260 + 256 + 480 + 48) * (int)sizeof(float);
    cudaFuncSetAttribute(main_kernel, cudaFuncAttributeMaxDynamicSharedMemorySize,
                         smem_bytes);
    main_kernel<<<NBLK, NT, smem_bytes>>>(state, fitness, pk, W1, b1, ln_g, ln_b,
                                          tcW, tcb, tccW, tccb, w_prev, out);
}

// round 4
// speedup vs baseline: 1.2691x; 1.0357x over previous
#include <cuda_runtime.h>
#include <math.h>

#define B_TOT 16384
#define S_DIM 300
#define A_DIM 30
#define EMB 256
#define M_PROTO 16
#define NT 256
#define ROWS 16
#define NBLK (B_TOT / ROWS)

// Precomputed batch-independent tables
__device__ float G_g[256 * 128];    // G[k][m*16+n], scale folded in
__device__ float c_g[128];          // c[m*16+n]
__device__ float conc_g[M_PROTO * A_DIM];

// ---------------------------------------------------------------------------
// Precompute: blocks 0..255 -> G row k; block 256 -> c_g + conc_g (parallel)
// ---------------------------------------------------------------------------
__global__ void __launch_bounds__(256) precompute_kernel(
    const float* __restrict__ pk, const float* __restrict__ enc_W2,
    const float* __restrict__ enc_b2, const float* __restrict__ dW1,
    const float* __restrict__ db1, const float* __restrict__ dW2,
    const float* __restrict__ db2) {
    const int bk = blockIdx.x;
    const int t = threadIdx.x;  // 256 threads
    if (bk < 256) {
        __shared__ float w2row[2048];
        __shared__ float pks[16 * 257];   // padded: conflict-free across n
        __shared__ float part[256];
        for (int i = t; i < 2048; i += 256) w2row[i] = enc_W2[bk * 2048 + i];
        for (int i = t; i < 4096; i += 256)
            pks[(i >> 8) * 257 + (i & 255)] = pk[i];
        __syncthreads();
        const int mn = t & 127, half = t >> 7;
        const int m = mn >> 4, n = mn & 15;
        const float* wr = w2row + m * 256 + half * 128;
        const float* pr = pks + n * 257 + half * 128;
        float s = 0.f;
        #pragma unroll 8
        for (int e = 0; e < 128; e++) s += wr[e] * pr[e];
        part[t] = s;
        __syncthreads();
        if (t < 128) G_g[bk * 128 + t] = (part[t] + part[t + 128]) * 0.0625f;
    } else {
        // ---- c_g: 128 outputs, split-e across 256 threads ----
        __shared__ float part[256];
        {
            const int mn = t & 127, half = t >> 7;
            const int m = mn >> 4, n = mn & 15;
            const float4* br = (const float4*)(enc_b2 + m * 256 + half * 128);
            const float4* pr = (const float4*)(pk + n * 256 + half * 128);
            float s = 0.f;
            #pragma unroll 8
            for (int e = 0; e < 32; e++) {
                const float4 b4 = __ldg(&br[e]);
                const float4 p4 = __ldg(&pr[e]);
                s += b4.x * p4.x + b4.y * p4.y + b4.z * p4.z + b4.w * p4.w;
            }
            part[t] = s;
            __syncthreads();
            if (t < 128) c_g[t] = (part[t] + part[t + 128]) * 0.0625f;
        }
        // ---- hd: 2048 outputs over 256 threads (coalesced over h) ----
        __shared__ float hd[M_PROTO * 128];
        {
            const int h = t & 127, mg = t >> 7;   // mg 0/1
            #pragma unroll
            for (int mm = 0; mm < 8; mm++) {
                const int m = mm * 2 + mg;
                float s = db1[m * 128 + h];
                const float* wcol = dW1 + (m * 256) * 128 + h;
                #pragma unroll 4
                for (int e = 0; e < 256; e++)
                    s += __ldg(pk + m * 256 + e) * __ldg(wcol + e * 128);
                hd[m * 128 + h] = fmaxf(s, 0.f);
            }
        }
        __syncthreads();
        // ---- conc: 480 outputs ----
        for (int idx = t; idx < M_PROTO * A_DIM; idx += 256) {
            const int m = idx / A_DIM, a = idx % A_DIM;
            float s = db2[m * A_DIM + a];
            #pragma unroll 4
            for (int h = 0; h < 128; h++)
                s += hd[m * 128 + h] * __ldg(dW2 + (m * 128 + h) * A_DIM + a);
            conc_g[idx] = fmaxf(s, 0.f) + log1pf(expf(-fabsf(s)));
        }
    }
}

// ---------------------------------------------------------------------------
// Main fused kernel: 1024 blocks x 256 threads, 16 batch rows per block
// ---------------------------------------------------------------------------
__global__ void __launch_bounds__(NT, 3) main_kernel(
    const float* __restrict__ state, const float* __restrict__ fitness,
    const float* __restrict__ pk, const float* __restrict__ W1,
    const float* __restrict__ b1, const float* __restrict__ ln_g,
    const float* __restrict__ ln_b, const float* __restrict__ tc_W,
    const float* __restrict__ tc_b, const float* __restrict__ tc_cW,
    const float* __restrict__ tc_cb, const float* __restrict__ w_prev,
    float* __restrict__ out) {
    extern __shared__ float sm[];
    float* st    = sm;                 // ROWS*304 = 4864  (later aliased by lgt)
    float* hbuf  = st + ROWS * 304;    // ROWS*256 = 4096
    float* dng   = hbuf + ROWS * 256;  // ROWS*260 = 4160 (padded, 16B-aligned)
    float* dds   = dng + ROWS * 260;   // 256
    float* concs = dds + 256;          // 480
    float* stats = concs + 480;        // 48: mu[16], rstd[16], crisis[16]
    float* lgt   = st;                 // alias: ROWS*128 (st dead by then)

    const int tid = threadIdx.x;
    const int lane = tid & 31;
    const int wid = tid >> 5;
    const int b0 = blockIdx.x * ROWS;
    const unsigned FULL = 0xffffffffu;

    // cooperative loads
    for (int i = tid; i < ROWS * S_DIM; i += NT) {
        int r = i / S_DIM, s = i - r * S_DIM;
        st[r * 304 + s] = state[(b0 + r) * S_DIM + s];
    }
    for (int i = tid; i < M_PROTO * A_DIM; i += NT) concs[i] = conc_g[i];
    __syncthreads();

    // ---- stage 1: market features + danger + crisis (warp per row pair) ----
    for (int rr = 0; rr < 2; rr++) {
        const int r = wid + rr * 8;
        const float* srow = st + r * 304;
        float p = 0.f, sh = 0.f;
        if (lane < 30) { p = srow[1 + lane]; sh = srow[31 + lane]; }
        float sp = p, spp = p * p, sps = p * sh;
        #pragma unroll
        for (int m2 = 16; m2 >= 1; m2 >>= 1) {
            sp  += __shfl_xor_sync(FULL, sp, m2);
            spp += __shfl_xor_sync(FULL, spp, m2);
            sps += __shfl_xor_sync(FULL, sps, m2);
        }
        const float bal = srow[0];
        const float mean = sp * (1.f / 30.f);
        const float var = fmaxf((spp - 30.f * mean * mean) * (1.f / 29.f), 0.f);
        const float stdv = sqrtf(var) + 1e-8f;
        const float tv = bal + sps;
        const float cash = bal / (tv + 1e-8f);
        float mf[12];
        mf[0] = bal; mf[1] = mean; mf[2] = stdv; mf[3] = cash;
        #pragma unroll
        for (int i = 0; i < 8; i++) mf[4 + i] = srow[61 + 30 * i];
        float cpart = 0.f;
        #pragma unroll
        for (int i = 0; i < 8; i++) {
            const int j = lane + 32 * i;
            float a = tc_b[j];
            #pragma unroll
            for (int f = 0; f < 12; f++) a += mf[f] * tc_W[f * 256 + j];
            const float d = tanhf(a);
            dng[r * 260 + j] = d;
            cpart += d * tc_cW[j];
        }
        #pragma unroll
        for (int m2 = 16; m2 >= 1; m2 >>= 1) cpart += __shfl_xor_sync(FULL, cpart, m2);
        if (lane == 0)
            stats[32 + r] = 1.f / (1.f + expf(-(cpart + tc_cb[0])));
    }
    __syncthreads();

    // ---- dd[r][n] = scale * danger[r] . pk[n]  (float4, pk via L2) ----
    {
        const int r = tid >> 4, n = tid & 15;
        const float* dr = dng + r * 260;
        const float4* pr = (const float4*)(pk + n * 256);
        float s = 0.f;
        #pragma unroll 4
        for (int k4 = 0; k4 < 64; k4++) {
            const float4 d4 = *(const float4*)&dr[k4 * 4];
            const float4 p4 = __ldg(&pr[k4]);
            s += d4.x * p4.x + d4.y * p4.y + d4.z * p4.z + d4.w * p4.w;
        }
        dds[r * 16 + n] = s * 0.0625f;
    }

    // ---- stage 2: enc_W1 GEMM, register tile 4 rows x 4 cols per thread ----
    // thread: cols c4..c4+3 (c4 = 4*(tid&63)), rows r0..r0+3 (r0 = 4*(tid>>6))
    {
        const int c4 = (tid & 63) * 4;
        const int r0 = (tid >> 6) * 4;
        float acc[4][4];
        #pragma unroll
        for (int r = 0; r < 4; r++)
            #pragma unroll
            for (int c = 0; c < 4; c++) acc[r][c] = 0.f;
        #pragma unroll 1
        for (int s = 0; s < S_DIM; s += 4) {
            float4 w0 = *(const float4*)&W1[(s + 0) * 256 + c4];
            float4 w1 = *(const float4*)&W1[(s + 1) * 256 + c4];
            float4 w2 = *(const float4*)&W1[(s + 2) * 256 + c4];
            float4 w3 = *(const float4*)&W1[(s + 3) * 256 + c4];
            #pragma unroll
            for (int r = 0; r < 4; r++) {
                const float4 sv = *(const float4*)&st[(r0 + r) * 304 + s];  // broadcast
                acc[r][0] += sv.x * w0.x + sv.y * w1.x + sv.z * w2.x + sv.w * w3.x;
                acc[r][1] += sv.x * w0.y + sv.y * w1.y + sv.z * w2.y + sv.w * w3.y;
                acc[r][2] += sv.x * w0.z + sv.y * w1.z + sv.z * w2.z + sv.w * w3.z;
                acc[r][3] += sv.x * w0.w + sv.y * w1.w + sv.z * w2.w + sv.w * w3.w;
            }
        }
        const float4 b4 = *(const float4*)&b1[c4];
        #pragma unroll
        for (int r = 0; r < 4; r++) {
            float4 o;
            o.x = acc[r][0] + b4.x; o.y = acc[r][1] + b4.y;
            o.z = acc[r][2] + b4.z; o.w = acc[r][3] + b4.w;
            *(float4*)&hbuf[(r0 + r) * 256 + c4] = o;
        }
    }
    __syncthreads();

    // ---- layernorm stats (warp per row pair) ----
    for (int rr = 0; rr < 2; rr++) {
        const int r = wid + rr * 8;
        float s1 = 0.f, s2 = 0.f;
        #pragma unroll
        for (int i = 0; i < 8; i++) {
            const float v = hbuf[r * 256 + lane + 32 * i];
            s1 += v; s2 += v * v;
        }
        #pragma unroll
        for (int m2 = 16; m2 >= 1; m2 >>= 1) {
            s1 += __shfl_xor_sync(FULL, s1, m2);
            s2 += __shfl_xor_sync(FULL, s2, m2);
        }
        if (lane == 0) {
            const float mu = s1 * (1.f / 256.f);
            const float var = s2 * (1.f / 256.f) - mu * mu;
            stats[r] = mu;
            stats[16 + r] = rsqrtf(fmaxf(var, 0.f) + 1e-5f);
        }
    }
    __syncthreads();
    {
        const float g = ln_g[tid], bb = ln_b[tid];
        #pragma unroll
        for (int r = 0; r < ROWS; r++) {
            const float v = (hbuf[r * 256 + tid] - stats[r]) * stats[16 + r] * g + bb;
            hbuf[r * 256 + tid] = fmaxf(v, 0.f);
        }
    }
    __syncthreads();

    // ---- folded logits GEMM: lgt[r][mn] = h[r].G[:,mn] + c + dd (k by 4) ----
    {
        const int mn = tid & 127, rg = tid >> 7;
        float acc[8];
        #pragma unroll
        for (int q = 0; q < 8; q++) acc[q] = 0.f;
        #pragma unroll 2
        for (int k4 = 0; k4 < 64; k4++) {
            const int k = k4 * 4;
            const float g0 = G_g[(k + 0) * 128 + mn];
            const float g1 = G_g[(k + 1) * 128 + mn];
            const float g2 = G_g[(k + 2) * 128 + mn];
            const float g3 = G_g[(k + 3) * 128 + mn];
            #pragma unroll
            for (int q = 0; q < 8; q++) {
                const float4 h4 = *(const float4*)&hbuf[(rg + 2 * q) * 256 + k];  // broadcast
                acc[q] += h4.x * g0 + h4.y * g1 + h4.z * g2 + h4.w * g3;
            }
        }
        const float cc = c_g[mn];
        const int n = mn & 15;
        #pragma unroll
        for (int q = 0; q < 8; q++) {
            const int r = rg + 2 * q;
            lgt[r * 128 + mn] = acc[q] + cc + dds[r * 16 + n];
        }
    }
    __syncthreads();

    // ---- softmax over protos, weight mixing, action softmax (warp/row) ----
    for (int rr = 0; rr < 2; rr++) {
        const int r = wid + rr * 8;
        const int n = lane & 15;
        const int mh = lane >> 4;
        float wot = 0.f;
        #pragma unroll
        for (int mm = 0; mm < 4; mm++) {
            const int m = mm * 2 + mh;
            const float v = lgt[r * 128 + m * 16 + n];
            float mx = v;
            #pragma unroll
            for (int m2 = 8; m2 >= 1; m2 >>= 1) mx = fmaxf(mx, __shfl_xor_sync(FULL, mx, m2));
            const float e = expf(v - mx);
            float s = e;
            #pragma unroll
            for (int m2 = 8; m2 >= 1; m2 >>= 1) s += __shfl_xor_sync(FULL, s, m2);
            wot += e / s;
        }
        wot += __shfl_xor_sync(FULL, wot, 16);
        wot *= 0.125f;

        const float f = fitness[(b0 + r) * 16 + n];
        float wr = w_prev[n] * expf(0.1f * f);
        float swr = wr;
        #pragma unroll
        for (int m2 = 8; m2 >= 1; m2 >>= 1) swr += __shfl_xor_sync(FULL, swr, m2);
        wr /= (swr + 1e-8f);

        const float crisis = stats[32 + r];
        const float alpha = 0.06f + 0.24f * (1.f - crisis);
        float w = alpha * wot + (1.f - alpha) * wr;
        float sw = w;
        #pragma unroll
        for (int m2 = 8; m2 >= 1; m2 >>= 1) sw += __shfl_xor_sync(FULL, sw, m2);
        w /= (sw + 1e-8f);
        if (lane < 16) dds[r * 16 + n] = w;
        __syncwarp();

        float mix = __int_as_float(0xff800000);
        if (lane < 30) {
            mix = 1.f;
            #pragma unroll
            for (int m = 0; m < 16; m++) mix += dds[r * 16 + m] * concs[m * 30 + lane];
        }
        float mx = mix;
        #pragma unroll
        for (int m2 = 16; m2 >= 1; m2 >>= 1) mx = fmaxf(mx, __shfl_xor_sync(FULL, mx, m2));
        float e = (lane < 30) ? expf(mix - mx) : 0.f;
        float s = e;
        #pragma unroll
        for (int m2 = 16; m2 >= 1; m2 >>= 1) s += __shfl_xor_sync(FULL, s, m2);
        float p = e / s;
        float sp = p;
        #pragma unroll
        for (int m2 = 16; m2 >= 1; m2 >>= 1) sp += __shfl_xor_sync(FULL, sp, m2);
        p = p / (sp + 1e-8f);
        if (lane < 30) out[(b0 + r) * 30 + lane] = p;
    }
}

// ---------------------------------------------------------------------------
extern "C" void kernel_launch(void* const* d_in, const int* in_sizes, int n_in,
                              void* d_out, int out_size) {
    const float* state   = (const float*)d_in[0];
    const float* fitness = (const float*)d_in[1];
    const float* pk      = (const float*)d_in[2];
    const float* W1      = (const float*)d_in[3];
    const float* b1      = (const float*)d_in[4];
    const float* ln_g    = (const float*)d_in[5];
    const float* ln_b    = (const float*)d_in[6];
    const float* W2      = (const float*)d_in[7];
    const float* b2      = (const float*)d_in[8];
    const float* dW1     = (const float*)d_in[9];
    const float* db1     = (const float*)d_in[10];
    const float* dW2     = (const float*)d_in[11];
    const float* db2     = (const float*)d_in[12];
    const float* tcW     = (const float*)d_in[13];
    const float* tcb     = (const float*)d_in[14];
    const float* tccW    = (const float*)d_in[15];
    const float* tccb    = (const float*)d_in[16];
    const float* w_prev  = (const float*)d_in[19];
    float* out = (float*)d_out;

    precompute_kernel<<<257, 256>>>(pk, W2, b2, dW1, db1, dW2, db2);

    const int smem_bytes =
        (ROWS * 304 + ROWS * 256 + ROWS * 260 + 256 + 480 + 48) * (int)sizeof(float);
    cudaFuncSetAttribute(main_kernel, cudaFuncAttributeMaxDynamicSharedMemorySize,
                         smem_bytes);
    main_kernel<<<NBLK, NT, smem_bytes>>>(state, fitness, pk, W1, b1, ln_g, ln_b,
                                          tcW, tcb, tccW, tccb, w_prev, out);
}

// round 5
// speedup vs baseline: 2.0488x; 1.6143x over previous
#include <cuda_runtime.h>
#include <math.h>

#define B_TOT 16384
#define S_DIM 300
#define A_DIM 30
#define EMB 256
#define M_PROTO 16
#define NT 256
#define ROWS 16
#define NBLK (B_TOT / ROWS)
#define DH 260   // shared stride for dng/hbuf union (16B-aligned rows)

// Precomputed batch-independent tables
__device__ float G_g[256 * 128];    // G[k][m*16+n], scale folded in
__device__ float c_g[128];          // c[m*16+n]
__device__ float conc_g[M_PROTO * A_DIM];

// ---------------------------------------------------------------------------
// Precompute: blocks 0..255 -> G row k; block 256 -> c_g;
//             blocks 257..272 -> hd[m] + conc_g[m] (one block per proto)
// ---------------------------------------------------------------------------
__global__ void __launch_bounds__(256) precompute_kernel(
    const float* __restrict__ pk, const float* __restrict__ enc_W2,
    const float* __restrict__ enc_b2, const float* __restrict__ dW1,
    const float* __restrict__ db1, const float* __restrict__ dW2,
    const float* __restrict__ db2) {
    const int bk = blockIdx.x;
    const int t = threadIdx.x;  // 256 threads
    if (bk < 256) {
        __shared__ float w2row[2048];
        __shared__ float pks[16 * 257];   // padded: conflict-free across n
        __shared__ float part[256];
        for (int i = t; i < 2048; i += 256) w2row[i] = enc_W2[bk * 2048 + i];
        for (int i = t; i < 4096; i += 256)
            pks[(i >> 8) * 257 + (i & 255)] = pk[i];
        __syncthreads();
        const int mn = t & 127, half = t >> 7;
        const int m = mn >> 4, n = mn & 15;
        const float* wr = w2row + m * 256 + half * 128;
        const float* pr = pks + n * 257 + half * 128;
        float s = 0.f;
        #pragma unroll 8
        for (int e = 0; e < 128; e++) s += wr[e] * pr[e];
        part[t] = s;
        __syncthreads();
        if (t < 128) G_g[bk * 128 + t] = (part[t] + part[t + 128]) * 0.0625f;
    } else if (bk == 256) {
        // ---- c_g: 128 outputs, split-e across 256 threads ----
        __shared__ float part[256];
        const int mn = t & 127, half = t >> 7;
        const int m = mn >> 4, n = mn & 15;
        const float4* br = (const float4*)(enc_b2 + m * 256 + half * 128);
        const float4* pr = (const float4*)(pk + n * 256 + half * 128);
        float s = 0.f;
        #pragma unroll 8
        for (int e = 0; e < 32; e++) {
            const float4 b4 = __ldg(&br[e]);
            const float4 p4 = __ldg(&pr[e]);
            s += b4.x * p4.x + b4.y * p4.y + b4.z * p4.z + b4.w * p4.w;
        }
        part[t] = s;
        __syncthreads();
        if (t < 128) c_g[t] = (part[t] + part[t + 128]) * 0.0625f;
    } else {
        // ---- blocks 257..272: hd[m] then conc_g[m][*] ----
        const int m = bk - 257;
        __shared__ float part[256];
        __shared__ float hd[128];
        const int h = t & 127, eh = t >> 7;
        const float* pkm = pk + m * 256 + eh * 128;
        const float* wcol = dW1 + (m * 256 + eh * 128) * 128 + h;
        float s = 0.f;
        #pragma unroll 8
        for (int e = 0; e < 128; e++) s += pkm[e] * wcol[e * 128];
        part[t] = s;
        __syncthreads();
        if (t < 128)
            hd[t] = fmaxf(part[t] + part[t + 128] + db1[m * 128 + t], 0.f);
        __syncthreads();
        if (t < A_DIM) {
            float s2 = db2[m * A_DIM + t];
            const float* w2 = dW2 + m * 128 * A_DIM + t;
            #pragma unroll 8
            for (int h2 = 0; h2 < 128; h2++)
                s2 += hd[h2] * __ldg(w2 + h2 * A_DIM);
            conc_g[m * A_DIM + t] = fmaxf(s2, 0.f) + log1pf(expf(-fabsf(s2)));
        }
    }
}

// ---------------------------------------------------------------------------
// Main fused kernel: 1024 blocks x 256 threads, 16 batch rows per block
// smem 39.2KB, target 4 blocks/SM
// ---------------------------------------------------------------------------
__global__ void __launch_bounds__(NT, 4) main_kernel(
    const float* __restrict__ state, const float* __restrict__ fitness,
    const float* __restrict__ pk, const float* __restrict__ W1,
    const float* __restrict__ b1, const float* __restrict__ ln_g,
    const float* __restrict__ ln_b, const float* __restrict__ tc_W,
    const float* __restrict__ tc_b, const float* __restrict__ tc_cW,
    const float* __restrict__ tc_cb, const float* __restrict__ w_prev,
    float* __restrict__ out) {
    extern __shared__ float sm[];
    float* st    = sm;                // ROWS*304 = 4864 (aliased by lgt later)
    float* dh    = st + ROWS * 304;   // ROWS*260: dng first, then hbuf (aliased)
    float* dds   = dh + ROWS * DH;    // 256
    float* concs = dds + 256;         // 480
    float* stats = concs + 480;       // 48: mu[16], rstd[16], crisis[16]
    float* lgt   = st;                // alias: ROWS*128 (st dead by then)

    const int tid = threadIdx.x;
    const int lane = tid & 31;
    const int wid = tid >> 5;
    const int b0 = blockIdx.x * ROWS;
    const unsigned FULL = 0xffffffffu;

    // cooperative loads
    for (int i = tid; i < ROWS * S_DIM; i += NT) {
        int r = i / S_DIM, s = i - r * S_DIM;
        st[r * 304 + s] = state[(b0 + r) * S_DIM + s];
    }
    for (int i = tid; i < M_PROTO * A_DIM; i += NT) concs[i] = conc_g[i];
    __syncthreads();

    // ---- stage 1: market features + danger + crisis (warp per row pair) ----
    for (int rr = 0; rr < 2; rr++) {
        const int r = wid + rr * 8;
        const float* srow = st + r * 304;
        float p = 0.f, sh = 0.f;
        if (lane < 30) { p = srow[1 + lane]; sh = srow[31 + lane]; }
        float sp = p, spp = p * p, sps = p * sh;
        #pragma unroll
        for (int m2 = 16; m2 >= 1; m2 >>= 1) {
            sp  += __shfl_xor_sync(FULL, sp, m2);
            spp += __shfl_xor_sync(FULL, spp, m2);
            sps += __shfl_xor_sync(FULL, sps, m2);
        }
        const float bal = srow[0];
        const float mean = sp * (1.f / 30.f);
        const float var = fmaxf((spp - 30.f * mean * mean) * (1.f / 29.f), 0.f);
        const float stdv = sqrtf(var) + 1e-8f;
        const float tv = bal + sps;
        const float cash = bal / (tv + 1e-8f);
        float mf[12];
        mf[0] = bal; mf[1] = mean; mf[2] = stdv; mf[3] = cash;
        #pragma unroll
        for (int i = 0; i < 8; i++) mf[4 + i] = srow[61 + 30 * i];
        float cpart = 0.f;
        #pragma unroll
        for (int i = 0; i < 8; i++) {
            const int j = lane + 32 * i;
            float a = tc_b[j];
            #pragma unroll
            for (int f = 0; f < 12; f++) a += mf[f] * tc_W[f * 256 + j];
            const float d = tanhf(a);
            dh[r * DH + j] = d;   // danger
            cpart += d * tc_cW[j];
        }
        #pragma unroll
        for (int m2 = 16; m2 >= 1; m2 >>= 1) cpart += __shfl_xor_sync(FULL, cpart, m2);
        if (lane == 0)
            stats[32 + r] = 1.f / (1.f + expf(-(cpart + tc_cb[0])));
    }
    __syncthreads();

    // ---- dd[r][n] = scale * danger[r] . pk[n]  (float4, pk via L2) ----
    {
        const int r = tid >> 4, n = tid & 15;
        const float* dr = dh + r * DH;
        const float4* pr = (const float4*)(pk + n * 256);
        float s = 0.f;
        #pragma unroll 4
        for (int k4 = 0; k4 < 64; k4++) {
            const float4 d4 = *(const float4*)&dr[k4 * 4];
            const float4 p4 = __ldg(&pr[k4]);
            s += d4.x * p4.x + d4.y * p4.y + d4.z * p4.z + d4.w * p4.w;
        }
        dds[r * 16 + n] = s * 0.0625f;
    }
    __syncthreads();   // danger region (dh) now dead -> reuse as hbuf

    // ---- stage 2: enc_W1 GEMM, 8 rows x 2 cols per thread ----
    // cols c2..c2+1 (c2 = 2*(tid&127)), rows r0..r0+7 (r0 = 8*(tid>>7))
    {
        const int c2 = (tid & 127) * 2;
        const int r0 = (tid >> 7) * 8;
        float acc[8][2];
        #pragma unroll
        for (int r = 0; r < 8; r++) { acc[r][0] = 0.f; acc[r][1] = 0.f; }
        #pragma unroll 1
        for (int s = 0; s < S_DIM; s += 4) {
            const float2 w0 = *(const float2*)&W1[(s + 0) * 256 + c2];
            const float2 w1 = *(const float2*)&W1[(s + 1) * 256 + c2];
            const float2 w2 = *(const float2*)&W1[(s + 2) * 256 + c2];
            const float2 w3 = *(const float2*)&W1[(s + 3) * 256 + c2];
            #pragma unroll
            for (int r = 0; r < 8; r++) {
                const float4 sv = *(const float4*)&st[(r0 + r) * 304 + s]; // broadcast
                acc[r][0] += sv.x * w0.x + sv.y * w1.x + sv.z * w2.x + sv.w * w3.x;
                acc[r][1] += sv.x * w0.y + sv.y * w1.y + sv.z * w2.y + sv.w * w3.y;
            }
        }
        const float2 b2v = *(const float2*)&b1[c2];
        #pragma unroll
        for (int r = 0; r < 8; r++) {
            float2 o;
            o.x = acc[r][0] + b2v.x;
            o.y = acc[r][1] + b2v.y;
            *(float2*)&dh[(r0 + r) * DH + c2] = o;   // hbuf
        }
    }
    __syncthreads();

    // ---- layernorm stats (warp per row pair) ----
    for (int rr = 0; rr < 2; rr++) {
        const int r = wid + rr * 8;
        float s1 = 0.f, s2 = 0.f;
        #pragma unroll
        for (int i = 0; i < 8; i++) {
            const float v = dh[r * DH + lane + 32 * i];
            s1 += v; s2 += v * v;
        }
        #pragma unroll
        for (int m2 = 16; m2 >= 1; m2 >>= 1) {
            s1 += __shfl_xor_sync(FULL, s1, m2);
            s2 += __shfl_xor_sync(FULL, s2, m2);
        }
        if (lane == 0) {
            const float mu = s1 * (1.f / 256.f);
            const float var = s2 * (1.f / 256.f) - mu * mu;
            stats[r] = mu;
            stats[16 + r] = rsqrtf(fmaxf(var, 0.f) + 1e-5f);
        }
    }
    __syncthreads();
    {
        const float g = ln_g[tid], bb = ln_b[tid];
        #pragma unroll
        for (int r = 0; r < ROWS; r++) {
            const float v = (dh[r * DH + tid] - stats[r]) * stats[16 + r] * g + bb;
            dh[r * DH + tid] = fmaxf(v, 0.f);
        }
    }
    __syncthreads();

    // ---- folded logits GEMM: lgt[r][mn] = h[r].G[:,mn] + c + dd (k by 4) ----
    {
        const int mn = tid & 127, rg = tid >> 7;
        float acc[8];
        #pragma unroll
        for (int q = 0; q < 8; q++) acc[q] = 0.f;
        #pragma unroll 2
        for (int k4 = 0; k4 < 64; k4++) {
            const int k = k4 * 4;
            const float g0 = G_g[(k + 0) * 128 + mn];
            const float g1 = G_g[(k + 1) * 128 + mn];
            const float g2 = G_g[(k + 2) * 128 + mn];
            const float g3 = G_g[(k + 3) * 128 + mn];
            #pragma unroll
            for (int q = 0; q < 8; q++) {
                const float4 h4 = *(const float4*)&dh[(rg + 2 * q) * DH + k]; // broadcast
                acc[q] += h4.x * g0 + h4.y * g1 + h4.z * g2 + h4.w * g3;
            }
        }
        const float cc = c_g[mn];
        const int n = mn & 15;
        #pragma unroll
        for (int q = 0; q < 8; q++) {
            const int r = rg + 2 * q;
            lgt[r * 128 + mn] = acc[q] + cc + dds[r * 16 + n];
        }
    }
    __syncthreads();

    // ---- softmax over protos, weight mixing, action softmax (warp/row) ----
    for (int rr = 0; rr < 2; rr++) {
        const int r = wid + rr * 8;
        const int n = lane & 15;
        const int mh = lane >> 4;
        float wot = 0.f;
        #pragma unroll
        for (int mm = 0; mm < 4; mm++) {
            const int m = mm * 2 + mh;
            const float v = lgt[r * 128 + m * 16 + n];
            float mx = v;
            #pragma unroll
            for (int m2 = 8; m2 >= 1; m2 >>= 1) mx = fmaxf(mx, __shfl_xor_sync(FULL, mx, m2));
            const float e = expf(v - mx);
            float s = e;
            #pragma unroll
            for (int m2 = 8; m2 >= 1; m2 >>= 1) s += __shfl_xor_sync(FULL, s, m2);
            wot += e / s;
        }
        wot += __shfl_xor_sync(FULL, wot, 16);
        wot *= 0.125f;

        const float f = fitness[(b0 + r) * 16 + n];
        float wr = w_prev[n] * expf(0.1f * f);
        float swr = wr;
        #pragma unroll
        for (int m2 = 8; m2 >= 1; m2 >>= 1) swr += __shfl_xor_sync(FULL, swr, m2);
        wr /= (swr + 1e-8f);

        const float crisis = stats[32 + r];
        const float alpha = 0.06f + 0.24f * (1.f - crisis);
        float w = alpha * wot + (1.f - alpha) * wr;
        float sw = w;
        #pragma unroll
        for (int m2 = 8; m2 >= 1; m2 >>= 1) sw += __shfl_xor_sync(FULL, sw, m2);
        w /= (sw + 1e-8f);
        if (lane < 16) dds[r * 16 + n] = w;
        __syncwarp();

        float mix = __int_as_float(0xff800000);
        if (lane < 30) {
            mix = 1.f;
            #pragma unroll
            for (int m = 0; m < 16; m++) mix += dds[r * 16 + m] * concs[m * 30 + lane];
        }
        float mx = mix;
        #pragma unroll
        for (int m2 = 16; m2 >= 1; m2 >>= 1) mx = fmaxf(mx, __shfl_xor_sync(FULL, mx, m2));
        float e = (lane < 30) ? expf(mix - mx) : 0.f;
        float s = e;
        #pragma unroll
        for (int m2 = 16; m2 >= 1; m2 >>= 1) s += __shfl_xor_sync(FULL, s, m2);
        float p = e / s;
        float sp = p;
        #pragma unroll
        for (int m2 = 16; m2 >= 1; m2 >>= 1) sp += __shfl_xor_sync(FULL, sp, m2);
        p = p / (sp + 1e-8f);
        if (lane < 30) out[(b0 + r) * 30 + lane] = p;
    }
}

// ---------------------------------------------------------------------------
extern "C" void kernel_launch(void* const* d_in, const int* in_sizes, int n_in,
                              void* d_out, int out_size) {
    const float* state   = (const float*)d_in[0];
    const float* fitness = (const float*)d_in[1];
    const float* pk      = (const float*)d_in[2];
    const float* W1      = (const float*)d_in[3];
    const float* b1      = (const float*)d_in[4];
    const float* ln_g    = (const float*)d_in[5];
    const float* ln_b    = (const float*)d_in[6];
    const float* W2      = (const float*)d_in[7];
    const float* b2      = (const float*)d_in[8];
    const float* dW1     = (const float*)d_in[9];
    const float* db1     = (const float*)d_in[10];
    const float* dW2     = (const float*)d_in[11];
    const float* db2     = (const float*)d_in[12];
    const float* tcW     = (const float*)d_in[13];
    const float* tcb     = (const float*)d_in[14];
    const float* tccW    = (const float*)d_in[15];
    const float* tccb    = (const float*)d_in[16];
    const float* w_prev  = (const float*)d_in[19];
    float* out = (float*)d_out;

    precompute_kernel<<<273, 256>>>(pk, W2, b2, dW1, db1, dW2, db2);

    const int smem_bytes =
        (ROWS * 304 + ROWS * DH + 256 + 480 + 48) * (int)sizeof(float);
    cudaFuncSetAttribute(main_kernel, cudaFuncAttributeMaxDynamicSharedMemorySize,
                         smem_bytes);
    main_kernel<<<NBLK, NT, smem_bytes>>>(state, fitness, pk, W1, b1, ln_g, ln_b,
                                          tcW, tcb, tccW, tccb, w_prev, out);
}

// round 6
// speedup vs baseline: 2.2462x; 1.0964x over previous
#include <cuda_runtime.h>
#include <math.h>

#define B_TOT 16384
#define S_DIM 300
#define A_DIM 30
#define EMB 256
#define M_PROTO 16
#define NT 256
#define ROWS 16
#define NBLK (B_TOT / ROWS)
#define DH 260   // row stride for dng/hbuf union (16B-aligned rows)

// Precomputed batch-independent tables
__device__ float G_g[256 * 128];    // G[k][m*16+n], scale folded in
__device__ float c_g[128];          // c[m*16+n]
__device__ float conc_g[M_PROTO * A_DIM];

// ---------------------------------------------------------------------------
// Precompute: blocks 0..255 -> G row k; block 256 -> c_g;
//             blocks 257..272 -> hd[m] + conc_g[m]
// ---------------------------------------------------------------------------
__global__ void __launch_bounds__(256) precompute_kernel(
    const float* __restrict__ pk, const float* __restrict__ enc_W2,
    const float* __restrict__ enc_b2, const float* __restrict__ dW1,
    const float* __restrict__ db1, const float* __restrict__ dW2,
    const float* __restrict__ db2) {
    const int bk = blockIdx.x;
    const int t = threadIdx.x;  // 256 threads
    if (bk < 256) {
        __shared__ float w2row[2048];
        __shared__ float pks[16 * 257];
        __shared__ float part[256];
        for (int i = t; i < 2048; i += 256) w2row[i] = enc_W2[bk * 2048 + i];
        for (int i = t; i < 4096; i += 256)
            pks[(i >> 8) * 257 + (i & 255)] = pk[i];
        __syncthreads();
        const int mn = t & 127, half = t >> 7;
        const int m = mn >> 4, n = mn & 15;
        const float* wr = w2row + m * 256 + half * 128;
        const float* pr = pks + n * 257 + half * 128;
        float s = 0.f;
        #pragma unroll 8
        for (int e = 0; e < 128; e++) s += wr[e] * pr[e];
        part[t] = s;
        __syncthreads();
        if (t < 128) G_g[bk * 128 + t] = (part[t] + part[t + 128]) * 0.0625f;
    } else if (bk == 256) {
        __shared__ float part[256];
        const int mn = t & 127, half = t >> 7;
        const int m = mn >> 4, n = mn & 15;
        const float4* br = (const float4*)(enc_b2 + m * 256 + half * 128);
        const float4* pr = (const float4*)(pk + n * 256 + half * 128);
        float s = 0.f;
        #pragma unroll 8
        for (int e = 0; e < 32; e++) {
            const float4 b4 = __ldg(&br[e]);
            const float4 p4 = __ldg(&pr[e]);
            s += b4.x * p4.x + b4.y * p4.y + b4.z * p4.z + b4.w * p4.w;
        }
        part[t] = s;
        __syncthreads();
        if (t < 128) c_g[t] = (part[t] + part[t + 128]) * 0.0625f;
    } else {
        const int m = bk - 257;
        __shared__ float part[256];
        __shared__ float hd[128];
        const int h = t & 127, eh = t >> 7;
        const float* pkm = pk + m * 256 + eh * 128;
        const float* wcol = dW1 + (m * 256 + eh * 128) * 128 + h;
        float s = 0.f;
        #pragma unroll 8
        for (int e = 0; e < 128; e++) s += pkm[e] * wcol[e * 128];
        part[t] = s;
        __syncthreads();
        if (t < 128)
            hd[t] = fmaxf(part[t] + part[t + 128] + db1[m * 128 + t], 0.f);
        __syncthreads();
        if (t < A_DIM) {
            float s2 = db2[m * A_DIM + t];
            const float* w2 = dW2 + m * 128 * A_DIM + t;
            #pragma unroll 8
            for (int h2 = 0; h2 < 128; h2++)
                s2 += hd[h2] * __ldg(w2 + h2 * A_DIM);
            conc_g[m * A_DIM + t] = fmaxf(s2, 0.f) + log1pf(expf(-fabsf(s2)));
        }
    }
}

// ---------------------------------------------------------------------------
// Main fused kernel: 1024 blocks x 256 threads, 16 batch rows per block
// ---------------------------------------------------------------------------
__global__ void __launch_bounds__(NT, 4) main_kernel(
    const float* __restrict__ state, const float* __restrict__ fitness,
    const float* __restrict__ pk, const float* __restrict__ W1,
    const float* __restrict__ b1, const float* __restrict__ ln_g,
    const float* __restrict__ ln_b, const float* __restrict__ tc_W,
    const float* __restrict__ tc_b, const float* __restrict__ tc_cW,
    const float* __restrict__ tc_cb, const float* __restrict__ w_prev,
    float* __restrict__ out) {
    extern __shared__ float sm[];
    float* st    = sm;                // ROWS*304 = 4864 (aliased by lgt later)
    float* dh    = st + ROWS * 304;   // ROWS*260: dng first, then hbuf (aliased)
    float* dds   = dh + ROWS * DH;    // 256
    float* concs = dds + 256;         // 480
    float* stats = concs + 480;       // 48: mu[16], rstd[16], crisis[16]
    float* lgt   = st;                // alias: ROWS*128 (st dead after W1)

    const int tid = threadIdx.x;
    const int lane = tid & 31;
    const int wid = tid >> 5;
    const int b0 = blockIdx.x * ROWS;
    const unsigned FULL = 0xffffffffu;

    // cooperative loads
    for (int i = tid; i < ROWS * S_DIM; i += NT) {
        int r = i / S_DIM, s = i - r * S_DIM;
        st[r * 304 + s] = state[(b0 + r) * S_DIM + s];
    }
    for (int i = tid; i < M_PROTO * A_DIM; i += NT) concs[i] = conc_g[i];
    __syncthreads();

    // ---- stage 1: market features + danger + crisis (warp per row pair) ----
    for (int rr = 0; rr < 2; rr++) {
        const int r = wid + rr * 8;
        const float* srow = st + r * 304;
        float p = 0.f, sh = 0.f;
        if (lane < 30) { p = srow[1 + lane]; sh = srow[31 + lane]; }
        float sp = p, spp = p * p, sps = p * sh;
        #pragma unroll
        for (int m2 = 16; m2 >= 1; m2 >>= 1) {
            sp  += __shfl_xor_sync(FULL, sp, m2);
            spp += __shfl_xor_sync(FULL, spp, m2);
            sps += __shfl_xor_sync(FULL, sps, m2);
        }
        const float bal = srow[0];
        const float mean = sp * (1.f / 30.f);
        const float var = fmaxf((spp - 30.f * mean * mean) * (1.f / 29.f), 0.f);
        const float stdv = sqrtf(var) + 1e-8f;
        const float tv = bal + sps;
        const float cash = bal / (tv + 1e-8f);
        float mf[12];
        mf[0] = bal; mf[1] = mean; mf[2] = stdv; mf[3] = cash;
        #pragma unroll
        for (int i = 0; i < 8; i++) mf[4 + i] = srow[61 + 30 * i];
        float cpart = 0.f;
        #pragma unroll
        for (int i = 0; i < 8; i++) {
            const int j = lane + 32 * i;
            float a = tc_b[j];
            #pragma unroll
            for (int f = 0; f < 12; f++) a += mf[f] * tc_W[f * 256 + j];
            const float d = tanhf(a);
            dh[r * DH + j] = d;   // danger
            cpart += d * tc_cW[j];
        }
        #pragma unroll
        for (int m2 = 16; m2 >= 1; m2 >>= 1) cpart += __shfl_xor_sync(FULL, cpart, m2);
        if (lane == 0)
            stats[32 + r] = 1.f / (1.f + expf(-(cpart + tc_cb[0])));
    }
    __syncthreads();

    // ---- dd[r][n]: thread = (n, kq); pk chunk cached in regs, read once ----
    {
        const int n = tid >> 4, kq = tid & 15;   // kq: 16-element k-chunk
        float pkc[16];
        {
            const float4* pr = (const float4*)(pk + n * 256 + kq * 16);
            #pragma unroll
            for (int i = 0; i < 4; i++) {
                const float4 p4 = __ldg(&pr[i]);
                pkc[i * 4 + 0] = p4.x; pkc[i * 4 + 1] = p4.y;
                pkc[i * 4 + 2] = p4.z; pkc[i * 4 + 3] = p4.w;
            }
        }
        #pragma unroll 4
        for (int r = 0; r < ROWS; r++) {
            const float* dr = dh + r * DH + kq * 16;
            float s = 0.f;
            #pragma unroll
            for (int i = 0; i < 4; i++) {
                const float4 d4 = *(const float4*)&dr[i * 4];
                s += d4.x * pkc[i * 4] + d4.y * pkc[i * 4 + 1] +
                     d4.z * pkc[i * 4 + 2] + d4.w * pkc[i * 4 + 3];
            }
            // reduce over 16-lane k-groups
            #pragma unroll
            for (int m2 = 8; m2 >= 1; m2 >>= 1) s += __shfl_xor_sync(FULL, s, m2);
            if (kq == 0) dds[r * 16 + n] = s * 0.0625f;
        }
    }
    __syncthreads();   // danger region (dh) now dead -> reuse as hbuf

    // ---- stage 2: enc_W1 GEMM, thread = column, 16 rows in regs ----
    {
        const int col = tid;
        float acc[ROWS];
        #pragma unroll
        for (int r = 0; r < ROWS; r++) acc[r] = 0.f;
        #pragma unroll 2
        for (int s = 0; s < S_DIM; s += 4) {
            const float w0 = W1[(s + 0) * 256 + col];
            const float w1 = W1[(s + 1) * 256 + col];
            const float w2 = W1[(s + 2) * 256 + col];
            const float w3 = W1[(s + 3) * 256 + col];
            #pragma unroll
            for (int r = 0; r < ROWS; r++) {
                const float4 sv = *(const float4*)&st[r * 304 + s];  // broadcast
                acc[r] += sv.x * w0 + sv.y * w1 + sv.z * w2 + sv.w * w3;
            }
        }
        const float bb = b1[col];
        #pragma unroll
        for (int r = 0; r < ROWS; r++) dh[r * DH + col] = acc[r] + bb;
    }
    __syncthreads();

    // ---- layernorm stats (warp per row pair) ----
    for (int rr = 0; rr < 2; rr++) {
        const int r = wid + rr * 8;
        float s1 = 0.f, s2 = 0.f;
        #pragma unroll
        for (int i = 0; i < 8; i++) {
            const float v = dh[r * DH + lane + 32 * i];
            s1 += v; s2 += v * v;
        }
        #pragma unroll
        for (int m2 = 16; m2 >= 1; m2 >>= 1) {
            s1 += __shfl_xor_sync(FULL, s1, m2);
            s2 += __shfl_xor_sync(FULL, s2, m2);
        }
        if (lane == 0) {
            const float mu = s1 * (1.f / 256.f);
            const float var = s2 * (1.f / 256.f) - mu * mu;
            stats[r] = mu;
            stats[16 + r] = rsqrtf(fmaxf(var, 0.f) + 1e-5f);
        }
    }
    __syncthreads();
    {
        const float g = ln_g[tid], bb = ln_b[tid];
        #pragma unroll
        for (int r = 0; r < ROWS; r++) {
            const float v = (dh[r * DH + tid] - stats[r]) * stats[16 + r] * g + bb;
            dh[r * DH + tid] = fmaxf(v, 0.f);
        }
    }
    __syncthreads();

    // ---- folded logits GEMM: split-k, thread = (mn, k-half), acc[16] ----
    {
        const int mn = tid & 127, kh = tid >> 7;
        float acc[ROWS];
        #pragma unroll
        for (int r = 0; r < ROWS; r++) acc[r] = 0.f;
        const int kbase = kh * 128;
        #pragma unroll 2
        for (int k4 = 0; k4 < 32; k4++) {
            const int k = kbase + k4 * 4;
            const float g0 = G_g[(k + 0) * 128 + mn];
            const float g1 = G_g[(k + 1) * 128 + mn];
            const float g2 = G_g[(k + 2) * 128 + mn];
            const float g3 = G_g[(k + 3) * 128 + mn];
            #pragma unroll
            for (int r = 0; r < ROWS; r++) {
                const float4 h4 = *(const float4*)&dh[r * DH + k];  // broadcast
                acc[r] += h4.x * g0 + h4.y * g1 + h4.z * g2 + h4.w * g3;
            }
        }
        if (kh == 1) {
            #pragma unroll
            for (int r = 0; r < ROWS; r++) lgt[r * 128 + mn] = acc[r];
        }
        __syncthreads();
        if (kh == 0) {
            const float cc = c_g[mn];
            const int n = mn & 15;
            #pragma unroll
            for (int r = 0; r < ROWS; r++)
                lgt[r * 128 + mn] = acc[r] + lgt[r * 128 + mn] + cc + dds[r * 16 + n];
        }
    }
    __syncthreads();

    // ---- softmax over protos, weight mixing, action softmax (warp/row) ----
    for (int rr = 0; rr < 2; rr++) {
        const int r = wid + rr * 8;
        const int n = lane & 15;
        const int mh = lane >> 4;
        float wot = 0.f;
        #pragma unroll
        for (int mm = 0; mm < 4; mm++) {
            const int m = mm * 2 + mh;
            const float v = lgt[r * 128 + m * 16 + n];
            float mx = v;
            #pragma unroll
            for (int m2 = 8; m2 >= 1; m2 >>= 1) mx = fmaxf(mx, __shfl_xor_sync(FULL, mx, m2));
            const float e = expf(v - mx);
            float s = e;
            #pragma unroll
            for (int m2 = 8; m2 >= 1; m2 >>= 1) s += __shfl_xor_sync(FULL, s, m2);
            wot += e / s;
        }
        wot += __shfl_xor_sync(FULL, wot, 16);
        wot *= 0.125f;

        const float f = fitness[(b0 + r) * 16 + n];
        float wr = w_prev[n] * expf(0.1f * f);
        float swr = wr;
        #pragma unroll
        for (int m2 = 8; m2 >= 1; m2 >>= 1) swr += __shfl_xor_sync(FULL, swr, m2);
        wr /= (swr + 1e-8f);

        const float crisis = stats[32 + r];
        const float alpha = 0.06f + 0.24f * (1.f - crisis);
        float w = alpha * wot + (1.f - alpha) * wr;
        float sw = w;
        #pragma unroll
        for (int m2 = 8; m2 >= 1; m2 >>= 1) sw += __shfl_xor_sync(FULL, sw, m2);
        w /= (sw + 1e-8f);
        if (lane < 16) dds[r * 16 + n] = w;
        __syncwarp();

        float mix = __int_as_float(0xff800000);
        if (lane < 30) {
            mix = 1.f;
            #pragma unroll
            for (int m = 0; m < 16; m++) mix += dds[r * 16 + m] * concs[m * 30 + lane];
        }
        float mx = mix;
        #pragma unroll
        for (int m2 = 16; m2 >= 1; m2 >>= 1) mx = fmaxf(mx, __shfl_xor_sync(FULL, mx, m2));
        float e = (lane < 30) ? expf(mix - mx) : 0.f;
        float s = e;
        #pragma unroll
        for (int m2 = 16; m2 >= 1; m2 >>= 1) s += __shfl_xor_sync(FULL, s, m2);
        float p = e / s;
        float sp = p;
        #pragma unroll
        for (int m2 = 16; m2 >= 1; m2 >>= 1) sp += __shfl_xor_sync(FULL, sp, m2);
        p = p / (sp + 1e-8f);
        if (lane < 30) out[(b0 + r) * 30 + lane] = p;
    }
}

// ---------------------------------------------------------------------------
extern "C" void kernel_launch(void* const* d_in, const int* in_sizes, int n_in,
                              void* d_out, int out_size) {
    const float* state   = (const float*)d_in[0];
    const float* fitness = (const float*)d_in[1];
    const float* pk      = (const float*)d_in[2];
    const float* W1      = (const float*)d_in[3];
    const float* b1      = (const float*)d_in[4];
    const float* ln_g    = (const float*)d_in[5];
    const float* ln_b    = (const float*)d_in[6];
    const float* W2      = (const float*)d_in[7];
    const float* b2      = (const float*)d_in[8];
    const float* dW1     = (const float*)d_in[9];
    const float* db1     = (const float*)d_in[10];
    const float* dW2     = (const float*)d_in[11];
    const float* db2     = (const float*)d_in[12];
    const float* tcW     = (const float*)d_in[13];
    const float* tcb     = (const float*)d_in[14];
    const float* tccW    = (const float*)d_in[15];
    const float* tccb    = (const float*)d_in[16];
    const float* w_prev  = (const float*)d_in[19];
    float* out = (float*)d_out;

    precompute_kernel<<<273, 256>>>(pk, W2, b2, dW1, db1, dW2, db2);

    const int smem_bytes =
        (ROWS * 304 + ROWS * DH + 256 + 480 + 48) * (int)sizeof(float);
    cudaFuncSetAttribute(main_kernel, cudaFuncAttributeMaxDynamicSharedMemorySize,
                         smem_bytes);
    main_kernel<<<NBLK, NT, smem_bytes>>>(state, fitness, pk, W1, b1, ln_g, ln_b,
                                          tcW, tcb, tccW, tccb, w_prev, out);
}